// round 5
// baseline (speedup 1.0000x reference)
#include <cuda_runtime.h>
#include <cuda_bf16.h>

// out[t,o] = y > remain[o] ? y : 0,   y = sum_i x[t,i] * w[o,i]
// x: [32768,1024] f32; w: [1024,1024] f32 (both K-contiguous -> NT GEMM);
// remain: [1024] f32; out: [32768,1024] f32.
//
// Bulk path: fp32 SIMT GEMM (128x128 tile, 8x8 microtile).
// Precision rescue: any accumulator within TAU of its threshold gets its
// dot product recomputed exactly in fp64 (f32*f32 is exact in f64), so the
// threshold DECISION matches the true value; only the reference's own
// rounding can disagree.

#define TOKENS   32768
#define DIN      1024
#define DOUT     1024

#define BM 128
#define BN 128
#define BK 16
#define TM 8
#define TN 8
#define NTHREADS 256
#define SM_LD (BM + 4)

#define TAU 2e-3f   // >> worst-case fp32 blocked-accumulation error for K=1024

// Exact-in-double recompute of one dot product (L2-hot data, rare path).
__device__ __noinline__ double exact_dot(const float* __restrict__ a,
                                         const float* __restrict__ b)
{
    double s = 0.0;
    #pragma unroll 1
    for (int k = 0; k < DIN; k += 4) {
        float4 av = *(const float4*)(a + k);
        float4 bv = *(const float4*)(b + k);
        s += (double)av.x * (double)bv.x;
        s += (double)av.y * (double)bv.y;
        s += (double)av.z * (double)bv.z;
        s += (double)av.w * (double)bv.w;
    }
    return s;
}

__global__ void __launch_bounds__(NTHREADS)
bio_gemm_remain_kernel(const float* __restrict__ A,      // x [M,K]
                       const float* __restrict__ W,      // w [N,K]
                       const float* __restrict__ remain, // [N]
                       float* __restrict__ C)            // out [M,N]
{
    __shared__ float As[BK][SM_LD];   // K-outer: As[k][m]
    __shared__ float Bs[BK][SM_LD];   // Bs[k][n]

    const int tid = threadIdx.x;
    const int m0  = blockIdx.y * BM;
    const int n0  = blockIdx.x * BN;

    const int lrow = tid >> 2;          // 0..63
    const int lcol = (tid & 3) << 2;    // 0,4,8,12

    const float* Ag = A + (size_t)(m0 + lrow) * DIN + lcol;
    const float* Bg = W + (size_t)(n0 + lrow) * DIN + lcol;

    const int mt = (tid >> 4) * TM;     // 0..120
    const int nt = (tid & 15) * TN;     // 0..120

    float acc[TM][TN];
    #pragma unroll
    for (int i = 0; i < TM; ++i)
        #pragma unroll
        for (int j = 0; j < TN; ++j) acc[i][j] = 0.0f;

    float4 a0 = *(const float4*)(Ag);
    float4 a1 = *(const float4*)(Ag + 64 * DIN);
    float4 b0 = *(const float4*)(Bg);
    float4 b1 = *(const float4*)(Bg + 64 * DIN);

    const int NT = DIN / BK;            // 64 K-slabs
    for (int kt = 0; kt < NT; ++kt) {
        As[lcol + 0][lrow]      = a0.x;
        As[lcol + 1][lrow]      = a0.y;
        As[lcol + 2][lrow]      = a0.z;
        As[lcol + 3][lrow]      = a0.w;
        As[lcol + 0][lrow + 64] = a1.x;
        As[lcol + 1][lrow + 64] = a1.y;
        As[lcol + 2][lrow + 64] = a1.z;
        As[lcol + 3][lrow + 64] = a1.w;
        Bs[lcol + 0][lrow]      = b0.x;
        Bs[lcol + 1][lrow]      = b0.y;
        Bs[lcol + 2][lrow]      = b0.z;
        Bs[lcol + 3][lrow]      = b0.w;
        Bs[lcol + 0][lrow + 64] = b1.x;
        Bs[lcol + 1][lrow + 64] = b1.y;
        Bs[lcol + 2][lrow + 64] = b1.z;
        Bs[lcol + 3][lrow + 64] = b1.w;
        __syncthreads();

        if (kt + 1 < NT) {
            const float* An = Ag + (kt + 1) * BK;
            const float* Bn = Bg + (kt + 1) * BK;
            a0 = *(const float4*)(An);
            a1 = *(const float4*)(An + 64 * DIN);
            b0 = *(const float4*)(Bn);
            b1 = *(const float4*)(Bn + 64 * DIN);
        }

        #pragma unroll
        for (int k = 0; k < BK; ++k) {
            float4 av0 = *(const float4*)&As[k][mt];
            float4 av1 = *(const float4*)&As[k][mt + 4];
            float4 bv0 = *(const float4*)&Bs[k][nt];
            float4 bv1 = *(const float4*)&Bs[k][nt + 4];
            float ar[TM] = {av0.x, av0.y, av0.z, av0.w,
                            av1.x, av1.y, av1.z, av1.w};
            float br[TN] = {bv0.x, bv0.y, bv0.z, bv0.w,
                            bv1.x, bv1.y, bv1.z, bv1.w};
            #pragma unroll
            for (int i = 0; i < TM; ++i)
                #pragma unroll
                for (int j = 0; j < TN; ++j)
                    acc[i][j] = fmaf(ar[i], br[j], acc[i][j]);
        }
        __syncthreads();
    }

    // ---- epilogue: threshold with fp64 rescue for near-threshold elements
    float rem[TN];
    #pragma unroll
    for (int j = 0; j < TN; ++j)
        rem[j] = __ldg(&remain[n0 + nt + j]);

    #pragma unroll
    for (int i = 0; i < TM; ++i) {
        const int row = m0 + mt + i;
        float* crow = C + (size_t)row * DOUT + (n0 + nt);
        float ov[TN];
        #pragma unroll
        for (int j = 0; j < TN; ++j) {
            float y = acc[i][j];
            float r = rem[j];
            if (fabsf(y - r) < TAU) {
                // rare: decide (and value) from the exact fp64 dot product
                double yd = exact_dot(A + (size_t)row * DIN,
                                      W + (size_t)(n0 + nt + j) * DIN);
                ov[j] = (yd > (double)r) ? (float)yd : 0.0f;
            } else {
                ov[j] = (y > r) ? y : 0.0f;
            }
        }
        float4 o0 = make_float4(ov[0], ov[1], ov[2], ov[3]);
        float4 o1 = make_float4(ov[4], ov[5], ov[6], ov[7]);
        *(float4*)(crow)     = o0;
        *(float4*)(crow + 4) = o1;
    }
}

extern "C" void kernel_launch(void* const* d_in, const int* in_sizes, int n_in,
                              void* d_out, int out_size)
{
    const float* x      = (const float*)d_in[0];   // [32768, 1024]
    const float* w      = (const float*)d_in[1];   // [1024, 1024]
    const float* remain = (const float*)d_in[2];   // [1024]
    float*       out    = (float*)d_out;           // [32768, 1024]

    dim3 grid(DOUT / BN, TOKENS / BM);  // (8, 256)
    dim3 block(NTHREADS);
    bio_gemm_remain_kernel<<<grid, block>>>(x, w, remain, out);
}